// round 4
// baseline (speedup 1.0000x reference)
#include <cuda_runtime.h>
#include <cuda_bf16.h>

// PairwiseDistances: d[e] = || R[idx_i[e]] - R[idx_j[e]] ||_2
// R: [N,3] f32; idx: **int32** [E] (JAX x64 disabled downcasts int64->int32);
// out: f32 [E]. E = 6,400,000 (divisible by 4).

__global__ __launch_bounds__(256) void pairwise_dist_kernel(
    const float* __restrict__ R,
    const int*   __restrict__ idx_i,
    const int*   __restrict__ idx_j,
    float* __restrict__ out,
    int num_quads)   // E/4
{
    int t = blockIdx.x * blockDim.x + threadIdx.x;
    if (t >= num_quads) return;

    // 16B vectorized index loads: 4 edges per thread.
    int4 i4 = __ldg(reinterpret_cast<const int4*>(idx_i) + t);
    int4 j4 = __ldg(reinterpret_cast<const int4*>(idx_j) + t);

    const float* Ri0 = R + 3 * (size_t)(unsigned)i4.x;
    const float* Ri1 = R + 3 * (size_t)(unsigned)i4.y;
    const float* Ri2 = R + 3 * (size_t)(unsigned)i4.z;
    const float* Ri3 = R + 3 * (size_t)(unsigned)i4.w;
    const float* Rj0 = R + 3 * (size_t)(unsigned)j4.x;
    const float* Rj1 = R + 3 * (size_t)(unsigned)j4.y;
    const float* Rj2 = R + 3 * (size_t)(unsigned)j4.z;
    const float* Rj3 = R + 3 * (size_t)(unsigned)j4.w;

    // 24 independent gathers, all L2-resident (R = 1.2 MB). High MLP.
    float ax0 = __ldg(Ri0+0), ay0 = __ldg(Ri0+1), az0 = __ldg(Ri0+2);
    float ax1 = __ldg(Ri1+0), ay1 = __ldg(Ri1+1), az1 = __ldg(Ri1+2);
    float ax2 = __ldg(Ri2+0), ay2 = __ldg(Ri2+1), az2 = __ldg(Ri2+2);
    float ax3 = __ldg(Ri3+0), ay3 = __ldg(Ri3+1), az3 = __ldg(Ri3+2);
    float bx0 = __ldg(Rj0+0), by0 = __ldg(Rj0+1), bz0 = __ldg(Rj0+2);
    float bx1 = __ldg(Rj1+0), by1 = __ldg(Rj1+1), bz1 = __ldg(Rj1+2);
    float bx2 = __ldg(Rj2+0), by2 = __ldg(Rj2+1), bz2 = __ldg(Rj2+2);
    float bx3 = __ldg(Rj3+0), by3 = __ldg(Rj3+1), bz3 = __ldg(Rj3+2);

    float dx0 = ax0-bx0, dy0 = ay0-by0, dz0 = az0-bz0;
    float dx1 = ax1-bx1, dy1 = ay1-by1, dz1 = az1-bz1;
    float dx2 = ax2-bx2, dy2 = ay2-by2, dz2 = az2-bz2;
    float dx3 = ax3-bx3, dy3 = ay3-by3, dz3 = az3-bz3;

    float4 o;
    o.x = sqrtf(fmaf(dx0, dx0, fmaf(dy0, dy0, dz0*dz0)));
    o.y = sqrtf(fmaf(dx1, dx1, fmaf(dy1, dy1, dz1*dz1)));
    o.z = sqrtf(fmaf(dx2, dx2, fmaf(dy2, dy2, dz2*dz2)));
    o.w = sqrtf(fmaf(dx3, dx3, fmaf(dy3, dy3, dz3*dz3)));

    reinterpret_cast<float4*>(out)[t] = o;
}

// Scalar tail for E % 4 != 0 (defensive; E=6.4M is divisible by 4).
__global__ void pairwise_dist_tail_kernel(
    const float* __restrict__ R,
    const int*   __restrict__ idx_i,
    const int*   __restrict__ idx_j,
    float* __restrict__ out,
    int start, int E)
{
    int e = start + blockIdx.x * blockDim.x + threadIdx.x;
    if (e >= E) return;
    int i = idx_i[e], j = idx_j[e];
    float dx = R[3*i+0] - R[3*j+0];
    float dy = R[3*i+1] - R[3*j+1];
    float dz = R[3*i+2] - R[3*j+2];
    out[e] = sqrtf(fmaf(dx, dx, fmaf(dy, dy, dz*dz)));
}

extern "C" void kernel_launch(void* const* d_in, const int* in_sizes, int n_in,
                              void* d_out, int out_size)
{
    const float* R     = (const float*)d_in[0];
    const int*   idx_i = (const int*)d_in[1];
    const int*   idx_j = (const int*)d_in[2];
    float*       out   = (float*)d_out;

    int E = in_sizes[1];          // number of edges
    int num_quads = E >> 2;

    const int threads = 256;
    int blocks = (num_quads + threads - 1) / threads;
    if (blocks > 0)
        pairwise_dist_kernel<<<blocks, threads>>>(R, idx_i, idx_j, out, num_quads);

    int tail = E & 3;
    if (tail)
        pairwise_dist_tail_kernel<<<1, 32>>>(R, idx_i, idx_j, out, E - tail, E);
}

// round 6
// speedup vs baseline: 1.3391x; 1.3391x over previous
#include <cuda_runtime.h>
#include <cuda_bf16.h>

// PairwiseDistances: d[e] = || R[idx_i[e]] - R[idx_j[e]] ||_2
// R: [N,3] f32 (N=100000); idx: int32 [E]; out: f32 [E]. E = 6,400,000.
//
// Strategy: pre-pad R into a 16B-aligned float4 table so each random gather
// is ONE LDG.128 hitting exactly one 32B L2 sector (vs 3 scalar LDGs = 3
// L1tex wavefront passes + possible sector straddle).

#define R4_CAP 131072  // 2 MB scratch; N=100000 fits

__device__ float4 g_R4[R4_CAP];

__global__ __launch_bounds__(256) void pad_R_kernel(
    const float* __restrict__ R, int n_atoms)
{
    int i = blockIdx.x * blockDim.x + threadIdx.x;
    if (i >= n_atoms) return;
    const float* r = R + 3 * (size_t)i;
    g_R4[i] = make_float4(r[0], r[1], r[2], 0.0f);
}

// Gather one padded row with L1 evict_last (keep table resident in L1
// against streaming index traffic). Plain (non-volatile) asm so ptxas can
// batch/reorder the 8 gathers for MLP.
__device__ __forceinline__ float4 ldg_row(int idx)
{
    float4 v;
    const float4* p = g_R4 + (unsigned)idx;
    asm("ld.global.nc.L1::evict_last.v4.f32 {%0,%1,%2,%3}, [%4];"
        : "=f"(v.x), "=f"(v.y), "=f"(v.z), "=f"(v.w)
        : "l"(p));
    return v;
}

__global__ __launch_bounds__(256) void pairwise_dist_kernel(
    const int*   __restrict__ idx_i,
    const int*   __restrict__ idx_j,
    float* __restrict__ out,
    int num_quads)   // E/4
{
    int t = blockIdx.x * blockDim.x + threadIdx.x;
    if (t >= num_quads) return;

    // 16B vectorized index loads: 4 edges per thread.
    int4 i4 = __ldg(reinterpret_cast<const int4*>(idx_i) + t);
    int4 j4 = __ldg(reinterpret_cast<const int4*>(idx_j) + t);

    // 8 independent 16B gathers — 1 L1tex wavefront + 1 L2 sector each.
    float4 a0 = ldg_row(i4.x);
    float4 a1 = ldg_row(i4.y);
    float4 a2 = ldg_row(i4.z);
    float4 a3 = ldg_row(i4.w);
    float4 b0 = ldg_row(j4.x);
    float4 b1 = ldg_row(j4.y);
    float4 b2 = ldg_row(j4.z);
    float4 b3 = ldg_row(j4.w);

    float dx0 = a0.x-b0.x, dy0 = a0.y-b0.y, dz0 = a0.z-b0.z;
    float dx1 = a1.x-b1.x, dy1 = a1.y-b1.y, dz1 = a1.z-b1.z;
    float dx2 = a2.x-b2.x, dy2 = a2.y-b2.y, dz2 = a2.z-b2.z;
    float dx3 = a3.x-b3.x, dy3 = a3.y-b3.y, dz3 = a3.z-b3.z;

    float4 o;
    o.x = sqrtf(fmaf(dx0, dx0, fmaf(dy0, dy0, dz0*dz0)));
    o.y = sqrtf(fmaf(dx1, dx1, fmaf(dy1, dy1, dz1*dz1)));
    o.z = sqrtf(fmaf(dx2, dx2, fmaf(dy2, dy2, dz2*dz2)));
    o.w = sqrtf(fmaf(dx3, dx3, fmaf(dy3, dy3, dz3*dz3)));

    reinterpret_cast<float4*>(out)[t] = o;
}

// Fallback (direct scalar gathers) if N exceeds scratch capacity.
__global__ __launch_bounds__(256) void pairwise_dist_direct_kernel(
    const float* __restrict__ R,
    const int*   __restrict__ idx_i,
    const int*   __restrict__ idx_j,
    float* __restrict__ out,
    int E)
{
    int e = blockIdx.x * blockDim.x + threadIdx.x;
    if (e >= E) return;
    int i = idx_i[e], j = idx_j[e];
    float dx = R[3*(size_t)i+0] - R[3*(size_t)j+0];
    float dy = R[3*(size_t)i+1] - R[3*(size_t)j+1];
    float dz = R[3*(size_t)i+2] - R[3*(size_t)j+2];
    out[e] = sqrtf(fmaf(dx, dx, fmaf(dy, dy, dz*dz)));
}

// Scalar tail for E % 4 != 0 (defensive; E=6.4M divisible by 4).
__global__ void pairwise_dist_tail_kernel(
    const int* __restrict__ idx_i,
    const int* __restrict__ idx_j,
    float* __restrict__ out,
    int start, int E)
{
    int e = start + blockIdx.x * blockDim.x + threadIdx.x;
    if (e >= E) return;
    float4 a = g_R4[(unsigned)idx_i[e]];
    float4 b = g_R4[(unsigned)idx_j[e]];
    float dx = a.x-b.x, dy = a.y-b.y, dz = a.z-b.z;
    out[e] = sqrtf(fmaf(dx, dx, fmaf(dy, dy, dz*dz)));
}

extern "C" void kernel_launch(void* const* d_in, const int* in_sizes, int n_in,
                              void* d_out, int out_size)
{
    const float* R     = (const float*)d_in[0];
    const int*   idx_i = (const int*)d_in[1];
    const int*   idx_j = (const int*)d_in[2];
    float*       out   = (float*)d_out;

    int n_atoms = in_sizes[0] / 3;
    int E = in_sizes[1];

    if (n_atoms > R4_CAP) {
        // Safe fallback: direct gather from unpadded R.
        int blocks = (E + 255) / 256;
        pairwise_dist_direct_kernel<<<blocks, 256>>>(R, idx_i, idx_j, out, E);
        return;
    }

    pad_R_kernel<<<(n_atoms + 255) / 256, 256>>>(R, n_atoms);

    int num_quads = E >> 2;
    int blocks = (num_quads + 255) / 256;
    if (blocks > 0)
        pairwise_dist_kernel<<<blocks, 256>>>(idx_i, idx_j, out, num_quads);

    int tail = E & 3;
    if (tail)
        pairwise_dist_tail_kernel<<<1, 32>>>(idx_i, idx_j, out, E - tail, E);
}